// round 1
// baseline (speedup 1.0000x reference)
#include <cuda_runtime.h>
#include <math.h>

#define Hn   2048
#define SEQ  2048
#define NBLK 148
#define TPB  256
#define CPT  8      // Hn / TPB columns per thread
#define MAXR 14     // max rows per block: ceil(2048/148)

// ------------------------------------------------------------------
// Static device scratch (no cudaMalloc allowed)
// ------------------------------------------------------------------
__device__ float d_XF[SEQ * Hn];   // x @ Wfx^T + bfx
__device__ float d_XH[SEQ * Hn];   // x @ Whx^T + bhx
__device__ float d_hbuf[Hn];       // current hidden state (global, cross-block)
__device__ float d_gbuf[Hn];       // f * h (global, cross-block)
__device__ unsigned d_bar_count = 0;
__device__ unsigned d_bar_gen   = 0;

// ------------------------------------------------------------------
// Grid barrier: sense-free monotonically increasing generation.
// All 148 blocks are co-resident (1 block/SM, smem-limited).
// ------------------------------------------------------------------
__device__ __forceinline__ void gbar(unsigned &bexp) {
    __threadfence();          // make this thread's global writes visible device-wide
    __syncthreads();
    bexp += 1;
    if (threadIdx.x == 0) {
        if (atomicAdd(&d_bar_count, 1u) == NBLK - 1) {
            d_bar_count = 0;
            __threadfence();
            atomicAdd(&d_bar_gen, 1u);
        } else {
            while ((int)(*(volatile unsigned *)&d_bar_gen - bexp) < 0) { }
        }
    }
    __syncthreads();
}

// ------------------------------------------------------------------
// Precompute GEMM:  C[s][n] = sum_k x[s][k] * W[n][k] + bias[n]
// blockIdx.z selects (Wfx,bfx)->d_XF or (Whx,bhx)->d_XH.
// 128x128 tile, BK=16, 8x8 per thread, 256 threads.
// ------------------------------------------------------------------
__global__ __launch_bounds__(256, 2) void mgu_gemm(
    const float* __restrict__ x,
    const float* __restrict__ Wfx, const float* __restrict__ bfx,
    const float* __restrict__ Whx, const float* __restrict__ bhx)
{
    const float* __restrict__ W    = (blockIdx.z == 0) ? Wfx : Whx;
    const float* __restrict__ bias = (blockIdx.z == 0) ? bfx : bhx;
    float* __restrict__ C          = (blockIdx.z == 0) ? d_XF : d_XH;

    __shared__ float As[16][132];
    __shared__ float Bs[16][132];

    const int bm  = blockIdx.y * 128;   // rows of x (s)
    const int bn  = blockIdx.x * 128;   // rows of W (output h)
    const int tid = threadIdx.x;
    const int tr  = (tid >> 4) << 3;    // 0..120 step 8
    const int tc  = (tid & 15) << 3;

    float acc[8][8];
#pragma unroll
    for (int i = 0; i < 8; i++)
#pragma unroll
        for (int j = 0; j < 8; j++) acc[i][j] = 0.f;

    for (int k0 = 0; k0 < 2048; k0 += 16) {
#pragma unroll
        for (int i = 0; i < 2; i++) {
            int q   = tid + (i << 8);        // 0..511
            int row = q >> 2;                // 0..127
            int kq  = (q & 3) << 2;          // 0,4,8,12
            float4 va = *(const float4 *)(x + (size_t)(bm + row) * 2048 + k0 + kq);
            As[kq + 0][row] = va.x; As[kq + 1][row] = va.y;
            As[kq + 2][row] = va.z; As[kq + 3][row] = va.w;
            float4 vb = *(const float4 *)(W + (size_t)(bn + row) * 2048 + k0 + kq);
            Bs[kq + 0][row] = vb.x; Bs[kq + 1][row] = vb.y;
            Bs[kq + 2][row] = vb.z; Bs[kq + 3][row] = vb.w;
        }
        __syncthreads();
#pragma unroll
        for (int k = 0; k < 16; k++) {
            float a[8], b[8];
            *(float4 *)(a)     = *(const float4 *)&As[k][tr];
            *(float4 *)(a + 4) = *(const float4 *)&As[k][tr + 4];
            *(float4 *)(b)     = *(const float4 *)&Bs[k][tc];
            *(float4 *)(b + 4) = *(const float4 *)&Bs[k][tc + 4];
#pragma unroll
            for (int i = 0; i < 8; i++)
#pragma unroll
                for (int j = 0; j < 8; j++) acc[i][j] += a[i] * b[j];
        }
        __syncthreads();
    }

    float bj[8];
#pragma unroll
    for (int j = 0; j < 8; j++) bj[j] = __ldg(&bias[bn + tc + j]);
#pragma unroll
    for (int i = 0; i < 8; i++) {
        float4 v0 = make_float4(acc[i][0] + bj[0], acc[i][1] + bj[1],
                                acc[i][2] + bj[2], acc[i][3] + bj[3]);
        float4 v1 = make_float4(acc[i][4] + bj[4], acc[i][5] + bj[5],
                                acc[i][6] + bj[6], acc[i][7] + bj[7]);
        size_t off = (size_t)(bm + tr + i) * 2048 + bn + tc;
        *(float4 *)(C + off)     = v0;
        *(float4 *)(C + off + 4) = v1;
    }
}

// ------------------------------------------------------------------
// Persistent scan kernel. Block b owns rows [r0,r1) of BOTH Wfh and
// Whf, cached in SMEM (<= 14 rows * 2 * 8KB = 224KB).
// Per step: phase A -> f, g = f*h published via L2; gbar;
//           phase B -> h_new published; gbar.
// Cross-block vectors read with __ldcg (bypass stale L1).
// ------------------------------------------------------------------
__global__ __launch_bounds__(TPB, 1) void mgu_scan(
    const float* __restrict__ h0,
    const float* __restrict__ Wfh, const float* __restrict__ bfh,
    const float* __restrict__ Whf, const float* __restrict__ bhf,
    float* __restrict__ out)
{
    extern __shared__ float sW[];
    __shared__ float sPart[MAXR][8];
    __shared__ float sF[MAXR];
    __shared__ float sHold[MAXR];
    __shared__ float sBfh[MAXR];
    __shared__ float sBhf[MAXR];

    const int b   = blockIdx.x;
    const int tid = threadIdx.x;
    const int r0  = (b * Hn) / NBLK;
    const int r1  = ((b + 1) * Hn) / NBLK;
    const int nr  = r1 - r0;               // 13 or 14

    float* sWf = sW;                        // Wfh rows
    float* sWh = sW + nr * Hn;              // Whf rows

    // load weight rows into SMEM (coalesced float4)
    {
        const float4* gf = (const float4 *)(Wfh + (size_t)r0 * Hn);
        const float4* gh = (const float4 *)(Whf + (size_t)r0 * Hn);
        float4* sf4 = (float4 *)sWf;
        float4* sh4 = (float4 *)sWh;
        const int n4 = nr * (Hn / 4);
        for (int i = tid; i < n4; i += TPB) { sf4[i] = gf[i]; sh4[i] = gh[i]; }
    }
    if (tid < nr) { sBfh[tid] = bfh[r0 + tid]; sBhf[tid] = bhf[r0 + tid]; }

    // init global hidden state
    for (int i = b * TPB + tid; i < Hn; i += NBLK * TPB) d_hbuf[i] = h0[i];

    unsigned bexp = 0;
    if (tid == 0) bexp = *(volatile unsigned *)&d_bar_gen;
    gbar(bexp);

    const int c0   = tid * CPT;
    const int wid  = tid >> 5;
    const int lane = tid & 31;

    for (int t = 0; t < SEQ; t++) {
        // ============ phase A : f = sigmoid(xf + Wfh h + bfh), g = f*h ======
        float xf_v = 0.f, h_own = 0.f;
        if (tid < nr) {
            xf_v  = __ldg(&d_XF[(size_t)t * Hn + r0 + tid]);
            h_own = __ldcg(&d_hbuf[r0 + tid]);
        }
        float4 hv0 = __ldcg((const float4 *)&d_hbuf[c0]);
        float4 hv1 = __ldcg((const float4 *)&d_hbuf[c0 + 4]);

        float acc[MAXR];
#pragma unroll
        for (int r = 0; r < MAXR; r++) acc[r] = 0.f;
#pragma unroll
        for (int r = 0; r < MAXR; r++) {
            if (r < nr) {
                const float4* wp = (const float4 *)(sWf + r * Hn + c0);
                float4 w0 = wp[0], w1 = wp[1];
                acc[r] = w0.x * hv0.x + w0.y * hv0.y + w0.z * hv0.z + w0.w * hv0.w
                       + w1.x * hv1.x + w1.y * hv1.y + w1.z * hv1.z + w1.w * hv1.w;
            }
        }
#pragma unroll
        for (int r = 0; r < MAXR; r++) {
            float v = acc[r];
            v += __shfl_xor_sync(0xffffffffu, v, 16);
            v += __shfl_xor_sync(0xffffffffu, v, 8);
            v += __shfl_xor_sync(0xffffffffu, v, 4);
            v += __shfl_xor_sync(0xffffffffu, v, 2);
            v += __shfl_xor_sync(0xffffffffu, v, 1);
            if (lane == 0) sPart[r][wid] = v;
        }
        __syncthreads();
        if (tid < nr) {
            float s = sPart[tid][0];
#pragma unroll
            for (int w = 1; w < 8; w++) s += sPart[tid][w];
            float z = s + sBfh[tid] + xf_v;
            float f = 1.f / (1.f + __expf(-z));
            sF[tid]    = f;
            sHold[tid] = h_own;
            d_gbuf[r0 + tid] = f * h_own;
        }
        gbar(bexp);

        // ============ phase B : h_hat = tanh(Whf g + bhf + xh); update =====
        float xh_v = 0.f;
        if (tid < nr) xh_v = __ldg(&d_XH[(size_t)t * Hn + r0 + tid]);
        float4 gv0 = __ldcg((const float4 *)&d_gbuf[c0]);
        float4 gv1 = __ldcg((const float4 *)&d_gbuf[c0 + 4]);

#pragma unroll
        for (int r = 0; r < MAXR; r++) acc[r] = 0.f;
#pragma unroll
        for (int r = 0; r < MAXR; r++) {
            if (r < nr) {
                const float4* wp = (const float4 *)(sWh + r * Hn + c0);
                float4 w0 = wp[0], w1 = wp[1];
                acc[r] = w0.x * gv0.x + w0.y * gv0.y + w0.z * gv0.z + w0.w * gv0.w
                       + w1.x * gv1.x + w1.y * gv1.y + w1.z * gv1.z + w1.w * gv1.w;
            }
        }
#pragma unroll
        for (int r = 0; r < MAXR; r++) {
            float v = acc[r];
            v += __shfl_xor_sync(0xffffffffu, v, 16);
            v += __shfl_xor_sync(0xffffffffu, v, 8);
            v += __shfl_xor_sync(0xffffffffu, v, 4);
            v += __shfl_xor_sync(0xffffffffu, v, 2);
            v += __shfl_xor_sync(0xffffffffu, v, 1);
            if (lane == 0) sPart[r][wid] = v;
        }
        __syncthreads();
        if (tid < nr) {
            float s = sPart[tid][0];
#pragma unroll
            for (int w = 1; w < 8; w++) s += sPart[tid][w];
            float hh = tanhf(s + sBhf[tid] + xh_v);
            float f  = sF[tid];
            float ho = sHold[tid];
            float hn = ho + f * (hh - ho);     // (1-f)*h + f*h_hat
            int row  = r0 + tid;
            out[(size_t)t * Hn + row] = hn;
            d_hbuf[row] = hn;
            if (t == SEQ - 1) out[(size_t)SEQ * Hn + row] = hn;  // h_final
        }
        gbar(bexp);
    }
}

// ------------------------------------------------------------------
extern "C" void kernel_launch(void* const* d_in, const int* in_sizes, int n_in,
                              void* d_out, int out_size)
{
    const float* x   = (const float *)d_in[0];
    const float* h0  = (const float *)d_in[1];
    const float* Wfx = (const float *)d_in[2];
    const float* bfx = (const float *)d_in[3];
    const float* Wfh = (const float *)d_in[4];
    const float* bfh = (const float *)d_in[5];
    const float* Whf = (const float *)d_in[6];
    const float* bhf = (const float *)d_in[7];
    const float* Whx = (const float *)d_in[8];
    const float* bhx = (const float *)d_in[9];
    float* out = (float *)d_out;

    (void)in_sizes; (void)n_in; (void)out_size;

    const size_t smem = (size_t)MAXR * Hn * 2 * sizeof(float);  // 229376 B
    cudaFuncSetAttribute(mgu_scan, cudaFuncAttributeMaxDynamicSharedMemorySize,
                         (int)smem);

    mgu_gemm<<<dim3(16, 16, 2), 256>>>(x, Wfx, bfx, Whx, bhx);
    mgu_scan<<<NBLK, TPB, smem>>>(h0, Wfh, bfh, Whf, bhf, out);
}